// round 11
// baseline (speedup 1.0000x reference)
#include <cuda_runtime.h>
#include <cuda_fp16.h>
#include <cstdint>

// Problem constants
#define BB   4
#define SS   2048
#define DD   1024
#define HH   16
#define HD   64
#define BS   (BB*SS)        // 8192

__device__ __forceinline__ uint32_t smem_u32(const void* p) {
    uint32_t a;
    asm("{ .reg .u64 t; cvta.to.shared.u64 t, %1; cvt.u32.u64 %0, t; }" : "=r"(a) : "l"(p));
    return a;
}
__device__ __forceinline__ void cp16(uint32_t dst, const void* src) {
    asm volatile("cp.async.cg.shared.global [%0], [%1], 16;" :: "r"(dst), "l"(src));
}
#define CP_COMMIT() asm volatile("cp.async.commit_group;" ::: "memory")
#define CP_WAIT0()  asm volatile("cp.async.wait_group 0;" ::: "memory")

// ---------------------------------------------------------------------------
// Scratch (device globals)
// ---------------------------------------------------------------------------
__device__ __half g_x16[(size_t)BS * DD];      // x fp16
__device__ __half g_w1[(size_t)(3*DD) * DD];   // W_in^T  [3072,1024] fp16
__device__ __half g_w2[(size_t)DD * DD];       // W_out^T [1024,1024] fp16
__device__ __half g_ph[(size_t)BS * 3 * DD];   // proj (k|q|v) fp16
__device__ __half g_pl[(size_t)BS * 3 * DD];   // proj lo (unused by attn now; written by GEMM1 split epilogue only if needed)
__device__ __half g_ah[(size_t)BS * DD];       // attention out fp16

// ---------------------------------------------------------------------------
// Prep kernels
// ---------------------------------------------------------------------------
__global__ __launch_bounds__(256) void conv_fp16(
    const float* __restrict__ src, __half* __restrict__ dst, int n4)
{
    int i = blockIdx.x * 256 + threadIdx.x;
    if (i >= n4) return;
    float4 v = ((const float4*)src)[i];
    ((__half2*)dst)[i*2+0] = __floats2half2_rn(v.x, v.y);
    ((__half2*)dst)[i*2+1] = __floats2half2_rn(v.z, v.w);
}

__global__ __launch_bounds__(256) void transpose_fp16(
    const float* __restrict__ W, __half* __restrict__ wt, int K, int N)
{
    __shared__ float tile[32][33];
    int k0 = blockIdx.y * 32, n0 = blockIdx.x * 32;
    int tx = threadIdx.x, ty = threadIdx.y;   // 32 x 8
#pragma unroll
    for (int j = 0; j < 32; j += 8)
        tile[ty + j][tx] = W[(size_t)(k0 + ty + j) * N + n0 + tx];
    __syncthreads();
#pragma unroll
    for (int j = 0; j < 32; j += 8)
        wt[(size_t)(n0 + ty + j) * K + k0 + tx] = __float2half_rn(tile[tx][ty + j]);
}

// ---------------------------------------------------------------------------
// mma.sync helpers
// ---------------------------------------------------------------------------
__device__ __forceinline__ void ldsm_x4(uint32_t& r0, uint32_t& r1, uint32_t& r2, uint32_t& r3,
                                        uint32_t addr) {
    asm volatile("ldmatrix.sync.aligned.m8n8.x4.shared.b16 {%0,%1,%2,%3}, [%4];"
                 : "=r"(r0), "=r"(r1), "=r"(r2), "=r"(r3) : "r"(addr));
}
__device__ __forceinline__ void ldsm_x4_t(uint32_t& r0, uint32_t& r1, uint32_t& r2, uint32_t& r3,
                                          uint32_t addr) {
    asm volatile("ldmatrix.sync.aligned.m8n8.x4.trans.shared.b16 {%0,%1,%2,%3}, [%4];"
                 : "=r"(r0), "=r"(r1), "=r"(r2), "=r"(r3) : "r"(addr));
}
__device__ __forceinline__ void mma_f16(float* d, const uint32_t* a, uint32_t b0, uint32_t b1) {
    asm volatile(
        "mma.sync.aligned.m16n8k16.row.col.f32.f16.f16.f32 "
        "{%0,%1,%2,%3}, {%4,%5,%6,%7}, {%8,%9}, {%0,%1,%2,%3};"
        : "+f"(d[0]), "+f"(d[1]), "+f"(d[2]), "+f"(d[3])
        : "r"(a[0]), "r"(a[1]), "r"(a[2]), "r"(a[3]), "r"(b0), "r"(b1));
}
__device__ __forceinline__ uint32_t pack_hi2(float x, float y) {
    __half2 t = __floats2half2_rn(x, y);
    return *(uint32_t*)&t;
}
__device__ __forceinline__ uint32_t pack_lo2(float x, float y) {
    float hx = __half2float(__float2half_rn(x));
    float hy = __half2float(__float2half_rn(y));
    __half2 t = __floats2half2_rn(x - hx, y - hy);
    return *(uint32_t*)&t;
}

// ---------------------------------------------------------------------------
// Persistent GEMM, fp16 x fp16, 256x128 CTA tile, 64x64 warp tiles,
// cp.async double buffer continuous across tiles, 1 CTA/SM.
// ---------------------------------------------------------------------------
#define PA  40
#define ASZ (256 * PA)
#define BSZ (128 * PA)
#define STG (ASZ + BSZ)   // fp16 elems per stage (15360)

__global__ __launch_bounds__(256, 1) void gemm_mma(
    const __half* __restrict__ Aa, const __half* __restrict__ Bw,
    const float* __restrict__ bias,
    float* __restrict__ C, __half* __restrict__ Ch,
    int M, int N, int K, int ntn)
{
    extern __shared__ __half sg[];   // 2 * STG
    const uint32_t uBase = smem_u32(sg);

    const int tid  = threadIdx.x;
    const int wid  = tid >> 5;
    const int lane = tid & 31;
    const int wrow = wid & 3;        // 4 m-warps * 64
    const int wcol = wid >> 2;       // 2 n-warps * 64
    const int quad = lane & 3, trow = lane >> 2;

    const int a_rl = (lane & 7) + ((lane >> 3) & 1) * 8;   // row within 16
    const int a_k  = (lane >> 4) * 8;
    const int b_rl = (lane >> 4) * 8 + (lane & 7);
    const int b_k  = ((lane >> 3) & 1) * 8;

    const int ntiles  = (M >> 8) * ntn;
    const int nchunks = K >> 5;

    auto load_chunk = [&](int t, int kc, int buf) {
        const int m0 = (t / ntn) << 8;
        const int n0 = (t % ntn) << 7;
        const int k0 = kc << 5;
        const __half* gA = Aa + (size_t)m0 * K + k0;
        const __half* gB = Bw + (size_t)n0 * K + k0;
        const uint32_t sb = uBase + buf * (STG * 2);
#pragma unroll
        for (int v = tid; v < 1536; v += 256) {
            if (v < 1024) {
                int r = v >> 2, c = v & 3;
                cp16(sb + (r * PA + c * 8) * 2, gA + (size_t)r * K + c * 8);
            } else {
                int idx = v - 1024;
                int r = idx >> 2, c = idx & 3;
                cp16(sb + (ASZ + r * PA + c * 8) * 2, gB + (size_t)r * K + c * 8);
            }
        }
    };

    int lt = blockIdx.x, lk = 0;
    if (lt < ntiles) { load_chunk(lt, 0, 0); CP_COMMIT(); lk = 1; }
    int gbuf = 0;

    for (int tile = blockIdx.x; tile < ntiles; tile += gridDim.x) {
        float acc[4][8][4];
#pragma unroll
        for (int i = 0; i < 4; i++)
#pragma unroll
            for (int j = 0; j < 8; j++)
#pragma unroll
                for (int v = 0; v < 4; v++) acc[i][j][v] = 0.f;

        for (int kc = 0; kc < nchunks; ++kc) {
            CP_WAIT0();
            __syncthreads();
            if (lt < ntiles) {
                load_chunk(lt, lk, gbuf ^ 1);
                CP_COMMIT();
                if (++lk == nchunks) { lk = 0; lt += gridDim.x; }
            }
            const uint32_t s0 = uBase + gbuf * (STG * 2);
            const uint32_t tA = s0;
            const uint32_t tB = s0 + ASZ * 2;

#pragma unroll
            for (int ks = 0; ks < 2; ks++) {
                uint32_t af[4][4];
#pragma unroll
                for (int mi = 0; mi < 4; mi++) {
                    uint32_t off = 2 * ((wrow * 64 + mi * 16 + a_rl) * PA + ks * 16 + a_k);
                    ldsm_x4(af[mi][0], af[mi][1], af[mi][2], af[mi][3], tA + off);
                }
#pragma unroll
                for (int j = 0; j < 4; j++) {
                    uint32_t off = 2 * ((wcol * 64 + j * 16 + b_rl) * PA + ks * 16 + b_k);
                    uint32_t b0, b1, b2, b3;
                    ldsm_x4(b0, b1, b2, b3, tB + off);
#pragma unroll
                    for (int mi = 0; mi < 4; mi++) {
                        mma_f16(acc[mi][2*j],   af[mi], b0, b1);
                        mma_f16(acc[mi][2*j+1], af[mi], b2, b3);
                    }
                }
            }
            gbuf ^= 1;
        }

        const int m0 = (tile / ntn) << 8;
        const int n0 = (tile % ntn) << 7;
#pragma unroll
        for (int mi = 0; mi < 4; mi++) {
            const int row0 = m0 + wrow * 64 + mi * 16 + trow;
#pragma unroll
            for (int nj = 0; nj < 8; nj++) {
                int c = n0 + wcol * 64 + quad * 2 + nj * 8;
                float2 bv = *(const float2*)(bias + c);
                float o00 = acc[mi][nj][0] + bv.x, o01 = acc[mi][nj][1] + bv.y;
                float o10 = acc[mi][nj][2] + bv.x, o11 = acc[mi][nj][3] + bv.y;
                size_t r0o = (size_t)row0 * N + c;
                size_t r1o = (size_t)(row0 + 8) * N + c;
                if (Ch) {
                    *(uint32_t*)(Ch + r0o) = pack_hi2(o00, o01);
                    *(uint32_t*)(Ch + r1o) = pack_hi2(o10, o11);
                } else {
                    *(float2*)(C + r0o) = make_float2(o00, o01);
                    *(float2*)(C + r1o) = make_float2(o10, o11);
                }
            }
        }
    }
}

// ---------------------------------------------------------------------------
// Flash-attention: Q, K, V single fp16; P split fp16 (hi+lo).
// 128-row tiles, cp.async double-buffered K/V.
// ---------------------------------------------------------------------------
#define PT 72
#define AT (128 * PT)      // one tile in fp16 elems (9216)
// smem: Q | stage0 (K|V) | stage1 (K|V) = 5 tiles
#define A_SMEM (5 * AT * 2)   // 92160 B

__global__ __launch_bounds__(256) void attn_mma(
    const __half* __restrict__ ph, __half* __restrict__ oh)
{
    extern __shared__ __half sb[];
    const uint32_t uBase = smem_u32(sb);
    const uint32_t uQ = uBase;

    const int qb = gridDim.x - 1 - blockIdx.x;   // heavy blocks first
    const int bh = blockIdx.y;
    const int b = bh / HH, h = bh % HH;
    const int tid = threadIdx.x, w = tid >> 5, lane = tid & 31;
    const int quad = lane & 3, trow = lane >> 2;

    const size_t rowstride = 3 * DD;
    const size_t rbase = (size_t)b * SS * rowstride;
    const int koff = h * HD, qoff = DD + h * HD, voff = 2 * DD + h * HD;

    // Q copy: 1 tile x 128 rows x 8 uint4
#pragma unroll
    for (int i = tid; i < 1024; i += 256) {
        int r = i >> 3, c = i & 7;
        cp16(uBase + (r * PT + c * 8) * 2,
             ph + rbase + (size_t)(qb * 128 + r) * rowstride + qoff + c * 8);
    }

    auto load_kv = [&](int kb, int buf) {
        const uint32_t sbs = uBase + (AT + buf * 2 * AT) * 2;
#pragma unroll
        for (int i = tid; i < 2048; i += 256) {
            int t = i >> 10, idx = i & 1023;
            int r = idx >> 3, c = idx & 7;
            int off = t ? voff : koff;
            cp16(sbs + (t * AT + r * PT + c * 8) * 2,
                 ph + rbase + (size_t)(kb * 128 + r) * rowstride + off + c * 8);
        }
    };

    load_kv(0, 0);
    CP_COMMIT();

    float acc_o[8][4];
#pragma unroll
    for (int j = 0; j < 8; j++)
#pragma unroll
        for (int v = 0; v < 4; v++) acc_o[j][v] = 0.f;
    float m0 = -1e30f, m1 = -1e30f, l0 = 0.f, l1 = 0.f;

    for (int kb = 0; kb <= qb; ++kb) {
        const int buf = kb & 1;
        CP_WAIT0();
        __syncthreads();
        if (kb < qb) {
            load_kv(kb + 1, buf ^ 1);
            CP_COMMIT();
        }
        const uint32_t s0 = uBase + (AT + buf * 2 * AT) * 2;
        const uint32_t uK = s0, uV = s0 + AT * 2;

        // ---- S = Q @ K^T : single-precision fp16 path ----
        float s[16][4];
#pragma unroll
        for (int j = 0; j < 16; j++)
#pragma unroll
            for (int v = 0; v < 4; v++) s[j][v] = 0.f;

#pragma unroll
        for (int kc = 0; kc < 4; kc++) {
            uint32_t qf[4];
            uint32_t aoff = 2 * ((w * 16 + (lane & 15)) * PT + kc * 16 + (lane >> 4) * 8);
            ldsm_x4(qf[0], qf[1], qf[2], qf[3], uQ + aoff);
#pragma unroll
            for (int ntp = 0; ntp < 8; ntp++) {
                uint32_t boff = 2 * ((ntp * 16 + (lane & 15)) * PT + kc * 16 + (lane >> 4) * 8);
                uint32_t k0r, k1r, k2r, k3r;
                ldsm_x4(k0r, k1r, k2r, k3r, uK + boff);
                mma_f16(s[2*ntp],   qf, k0r, k2r);
                mma_f16(s[2*ntp+1], qf, k1r, k3r);
            }
        }

        // scale 1/8
#pragma unroll
        for (int nt = 0; nt < 16; nt++) {
            s[nt][0] *= 0.125f; s[nt][1] *= 0.125f;
            s[nt][2] *= 0.125f; s[nt][3] *= 0.125f;
        }

        // causal mask (diagonal block only)
        if (kb == qb) {
            const int rl0 = w * 16 + trow;
#pragma unroll
            for (int nt = 0; nt < 16; nt++) {
                int c0 = nt * 8 + 2 * quad;
                if (c0 > rl0)     s[nt][0] = -1e30f;
                if (c0 + 1 > rl0) s[nt][1] = -1e30f;
                if (c0 > rl0 + 8)     s[nt][2] = -1e30f;
                if (c0 + 1 > rl0 + 8) s[nt][3] = -1e30f;
            }
        }

        // ---- online softmax ----
        float mx0 = -1e30f, mx1 = -1e30f;
#pragma unroll
        for (int nt = 0; nt < 16; nt++) {
            mx0 = fmaxf(mx0, fmaxf(s[nt][0], s[nt][1]));
            mx1 = fmaxf(mx1, fmaxf(s[nt][2], s[nt][3]));
        }
        mx0 = fmaxf(mx0, __shfl_xor_sync(0xffffffffu, mx0, 1));
        mx0 = fmaxf(mx0, __shfl_xor_sync(0xffffffffu, mx0, 2));
        mx1 = fmaxf(mx1, __shfl_xor_sync(0xffffffffu, mx1, 1));
        mx1 = fmaxf(mx1, __shfl_xor_sync(0xffffffffu, mx1, 2));
        float m0n = fmaxf(m0, mx0), m1n = fmaxf(m1, mx1);
        float al0 = __expf(m0 - m0n), al1 = __expf(m1 - m1n);
        m0 = m0n; m1 = m1n;

        float sum0 = 0.f, sum1 = 0.f;
#pragma unroll
        for (int nt = 0; nt < 16; nt++) {
            s[nt][0] = __expf(s[nt][0] - m0); sum0 += s[nt][0];
            s[nt][1] = __expf(s[nt][1] - m0); sum0 += s[nt][1];
            s[nt][2] = __expf(s[nt][2] - m1); sum1 += s[nt][2];
            s[nt][3] = __expf(s[nt][3] - m1); sum1 += s[nt][3];
        }
        sum0 += __shfl_xor_sync(0xffffffffu, sum0, 1);
        sum0 += __shfl_xor_sync(0xffffffffu, sum0, 2);
        sum1 += __shfl_xor_sync(0xffffffffu, sum1, 1);
        sum1 += __shfl_xor_sync(0xffffffffu, sum1, 2);
        l0 = l0 * al0 + sum0;
        l1 = l1 * al1 + sum1;

#pragma unroll
        for (int j = 0; j < 8; j++) {
            acc_o[j][0] *= al0; acc_o[j][1] *= al0;
            acc_o[j][2] *= al1; acc_o[j][3] *= al1;
        }

        // ---- O += P @ V : P split fp16 vs single V ----
#pragma unroll
        for (int kc = 0; kc < 8; kc++) {
            uint32_t pha[4], pla[4];
            pha[0] = pack_hi2(s[2*kc][0],   s[2*kc][1]);
            pha[1] = pack_hi2(s[2*kc][2],   s[2*kc][3]);
            pha[2] = pack_hi2(s[2*kc+1][0], s[2*kc+1][1]);
            pha[3] = pack_hi2(s[2*kc+1][2], s[2*kc+1][3]);
            pla[0] = pack_lo2(s[2*kc][0],   s[2*kc][1]);
            pla[1] = pack_lo2(s[2*kc][2],   s[2*kc][3]);
            pla[2] = pack_lo2(s[2*kc+1][0], s[2*kc+1][1]);
            pla[3] = pack_lo2(s[2*kc+1][2], s[2*kc+1][3]);
#pragma unroll
            for (int ht = 0; ht < 4; ht++) {
                uint32_t v0, v1, v2, v3;
                uint32_t off = 2 * ((kc * 16 + (lane & 15)) * PT + ht * 16 + (lane >> 4) * 8);
                ldsm_x4_t(v0, v1, v2, v3, uV + off);
                mma_f16(acc_o[2*ht],   pha, v0, v1);
                mma_f16(acc_o[2*ht+1], pha, v2, v3);
                mma_f16(acc_o[2*ht],   pla, v0, v1);
                mma_f16(acc_o[2*ht+1], pla, v2, v3);
            }
        }
    }

    // normalize and write fp16 output
    const float inv0 = 1.f / l0, inv1 = 1.f / l1;
    const size_t grow0 = (size_t)(b * SS + qb * 128 + w * 16 + trow);
    const size_t grow1 = grow0 + 8;
#pragma unroll
    for (int j = 0; j < 8; j++) {
        int c = h * HD + j * 8 + 2 * quad;
        *(uint32_t*)(oh + grow0 * DD + c) = pack_hi2(acc_o[j][0] * inv0, acc_o[j][1] * inv0);
        *(uint32_t*)(oh + grow1 * DD + c) = pack_hi2(acc_o[j][2] * inv1, acc_o[j][3] * inv1);
    }
}

// ---------------------------------------------------------------------------
extern "C" void kernel_launch(void* const* d_in, const int* in_sizes, int n_in,
                              void* d_out, int out_size)
{
    const float* x     = (const float*)d_in[0];
    const float* W_in  = (const float*)d_in[1];
    const float* b_in  = (const float*)d_in[2];
    const float* W_out = (const float*)d_in[3];
    const float* b_out = (const float*)d_in[4];
    float* out = (float*)d_out;

    __half *x16, *w1, *w2, *ph, *ah;
    cudaGetSymbolAddress((void**)&x16, g_x16);
    cudaGetSymbolAddress((void**)&w1, g_w1);
    cudaGetSymbolAddress((void**)&w2, g_w2);
    cudaGetSymbolAddress((void**)&ph, g_ph);
    cudaGetSymbolAddress((void**)&ah, g_ah);

    const int gemm_smem = 2 * STG * (int)sizeof(__half);   // 61440
    cudaFuncSetAttribute(gemm_mma, cudaFuncAttributeMaxDynamicSharedMemorySize, gemm_smem);
    cudaFuncSetAttribute(attn_mma, cudaFuncAttributeMaxDynamicSharedMemorySize, A_SMEM);

    // prep
    conv_fp16<<<(BS * DD / 4 + 255) / 256, 256>>>(x, x16, BS * DD / 4);
    transpose_fp16<<<dim3(3 * DD / 32, DD / 32), dim3(32, 8)>>>(W_in, w1, DD, 3 * DD);
    transpose_fp16<<<dim3(DD / 32, DD / 32), dim3(32, 8)>>>(W_out, w2, DD, DD);

    const int PGRID = 152;   // 1 per SM

    // 1) QKV projection -> fp16 proj (persistent)
    gemm_mma<<<PGRID, 256, gemm_smem>>>(
        x16, w1, b_in, nullptr, ph, BS, 3 * DD, DD, 3 * DD / 128);

    // 2) attention (Q/K/V fp16, P split) -> fp16 out
    {
        dim3 grid(SS / 128, BB * HH);
        attn_mma<<<grid, 256, A_SMEM>>>(ph, ah);
    }

    // 3) output projection -> fp32 out (persistent)
    gemm_mma<<<PGRID, 256, gemm_smem>>>(
        ah, w2, b_out, out, nullptr, BS, DD, DD, DD / 128);
}

// round 12
// speedup vs baseline: 1.2920x; 1.2920x over previous
#include <cuda_runtime.h>
#include <cuda_fp16.h>
#include <cstdint>

// Problem constants
#define BB   4
#define SS   2048
#define DD   1024
#define HH   16
#define HD   64
#define BS   (BB*SS)        // 8192

__device__ __forceinline__ uint32_t smem_u32(const void* p) {
    uint32_t a;
    asm("{ .reg .u64 t; cvta.to.shared.u64 t, %1; cvt.u32.u64 %0, t; }" : "=r"(a) : "l"(p));
    return a;
}
__device__ __forceinline__ void cp16(uint32_t dst, const void* src) {
    asm volatile("cp.async.cg.shared.global [%0], [%1], 16;" :: "r"(dst), "l"(src));
}
#define CP_COMMIT() asm volatile("cp.async.commit_group;" ::: "memory")
#define CP_WAIT0()  asm volatile("cp.async.wait_group 0;" ::: "memory")

// ---------------------------------------------------------------------------
// Scratch (device globals)
// ---------------------------------------------------------------------------
__device__ __half g_x16[(size_t)BS * DD];      // x fp16
__device__ __half g_w1[(size_t)(3*DD) * DD];   // W_in^T  [3072,1024] fp16
__device__ __half g_w2[(size_t)DD * DD];       // W_out^T [1024,1024] fp16
__device__ __half g_ph[(size_t)BS * 3 * DD];   // proj (k|q|v) fp16
__device__ __half g_ah[(size_t)BS * DD];       // attention out fp16

// ---------------------------------------------------------------------------
// Prep kernels
// ---------------------------------------------------------------------------
__global__ __launch_bounds__(256) void conv_fp16(
    const float* __restrict__ src, __half* __restrict__ dst, int n4)
{
    int i = blockIdx.x * 256 + threadIdx.x;
    if (i >= n4) return;
    float4 v = ((const float4*)src)[i];
    ((__half2*)dst)[i*2+0] = __floats2half2_rn(v.x, v.y);
    ((__half2*)dst)[i*2+1] = __floats2half2_rn(v.z, v.w);
}

__global__ __launch_bounds__(256) void transpose_fp16(
    const float* __restrict__ W, __half* __restrict__ wt, int K, int N)
{
    __shared__ float tile[32][33];
    int k0 = blockIdx.y * 32, n0 = blockIdx.x * 32;
    int tx = threadIdx.x, ty = threadIdx.y;   // 32 x 8
#pragma unroll
    for (int j = 0; j < 32; j += 8)
        tile[ty + j][tx] = W[(size_t)(k0 + ty + j) * N + n0 + tx];
    __syncthreads();
#pragma unroll
    for (int j = 0; j < 32; j += 8)
        wt[(size_t)(n0 + ty + j) * K + k0 + tx] = __float2half_rn(tile[tx][ty + j]);
}

// ---------------------------------------------------------------------------
// mma.sync helpers
// ---------------------------------------------------------------------------
__device__ __forceinline__ void ldsm_x4(uint32_t& r0, uint32_t& r1, uint32_t& r2, uint32_t& r3,
                                        uint32_t addr) {
    asm volatile("ldmatrix.sync.aligned.m8n8.x4.shared.b16 {%0,%1,%2,%3}, [%4];"
                 : "=r"(r0), "=r"(r1), "=r"(r2), "=r"(r3) : "r"(addr));
}
__device__ __forceinline__ void ldsm_x4_t(uint32_t& r0, uint32_t& r1, uint32_t& r2, uint32_t& r3,
                                          uint32_t addr) {
    asm volatile("ldmatrix.sync.aligned.m8n8.x4.trans.shared.b16 {%0,%1,%2,%3}, [%4];"
                 : "=r"(r0), "=r"(r1), "=r"(r2), "=r"(r3) : "r"(addr));
}
__device__ __forceinline__ void mma_f16(float* d, const uint32_t* a, uint32_t b0, uint32_t b1) {
    asm volatile(
        "mma.sync.aligned.m16n8k16.row.col.f32.f16.f16.f32 "
        "{%0,%1,%2,%3}, {%4,%5,%6,%7}, {%8,%9}, {%0,%1,%2,%3};"
        : "+f"(d[0]), "+f"(d[1]), "+f"(d[2]), "+f"(d[3])
        : "r"(a[0]), "r"(a[1]), "r"(a[2]), "r"(a[3]), "r"(b0), "r"(b1));
}
__device__ __forceinline__ uint32_t pack_hi2(float x, float y) {
    __half2 t = __floats2half2_rn(x, y);
    return *(uint32_t*)&t;
}

// ---------------------------------------------------------------------------
// GEMM on mma.sync: C = A @ B^T + bias, both single fp16.
// 128x128 tile, BK=32, cp.async double buffer, 2 CTAs/SM.  (R10 config)
// ---------------------------------------------------------------------------
#define PA 40
#define STG (2 * 128 * PA)   // fp16 elems per stage (A | B)

__global__ __launch_bounds__(256, 2) void gemm_mma(
    const __half* __restrict__ Aa, const __half* __restrict__ Bw,
    const float* __restrict__ bias,
    float* __restrict__ C, __half* __restrict__ Ch,
    int M, int N, int K)
{
    extern __shared__ __half sg[];   // 2 * STG
    const uint32_t uBase = smem_u32(sg);

    const int tid  = threadIdx.x;
    const int wid  = tid >> 5;
    const int lane = tid & 31;
    const int wrow = wid & 3;
    const int wcol = wid >> 2;
    const int m0 = blockIdx.y * 128;
    const int n0 = blockIdx.x * 128;

    const int a_row = wrow * 32 + (lane & 7) + ((lane >> 3) & 1) * 8;
    const int a_k   = (lane >> 4) * 8;
    const int b_row = wcol * 64 + (lane >> 4) * 8 + (lane & 7);
    const int b_k   = ((lane >> 3) & 1) * 8;

    const __half* gsrc[2] = { Aa + (size_t)m0 * K, Bw + (size_t)n0 * K };

    auto load_stage = [&](int kc, int buf) {
        const int k0 = kc << 5;
        const uint32_t sb = uBase + buf * (STG * 2);
#pragma unroll
        for (int v = tid; v < 1024; v += 256) {
            int t = v >> 9, idx = v & 511;
            int r = idx >> 2, c = idx & 3;
            cp16(sb + (t * (128 * PA) + r * PA + c * 8) * 2,
                 gsrc[t] + (size_t)r * K + k0 + c * 8);
        }
    };

    float acc[2][8][4];
#pragma unroll
    for (int i = 0; i < 2; i++)
#pragma unroll
        for (int j = 0; j < 8; j++)
#pragma unroll
            for (int v = 0; v < 4; v++) acc[i][j][v] = 0.f;

    const int nchunks = K >> 5;
    load_stage(0, 0);
    CP_COMMIT();

    for (int kc = 0; kc < nchunks; ++kc) {
        const int buf = kc & 1;
        CP_WAIT0();
        __syncthreads();
        if (kc + 1 < nchunks) {
            load_stage(kc + 1, buf ^ 1);
            CP_COMMIT();
        }
        const uint32_t s0 = uBase + buf * (STG * 2);
        const uint32_t tA = s0;
        const uint32_t tB = s0 + (128 * PA) * 2;

#pragma unroll
        for (int ks = 0; ks < 2; ks++) {
            uint32_t ah[2][4];
#pragma unroll
            for (int mi = 0; mi < 2; mi++) {
                uint32_t off = 2 * ((a_row + mi * 16) * PA + ks * 16 + a_k);
                ldsm_x4(ah[mi][0], ah[mi][1], ah[mi][2], ah[mi][3], tA + off);
            }
#pragma unroll
            for (int j = 0; j < 4; j++) {
                uint32_t off = 2 * ((b_row + j * 16) * PA + ks * 16 + b_k);
                uint32_t b0, b1, b2, b3;
                ldsm_x4(b0, b1, b2, b3, tB + off);
#pragma unroll
                for (int mi = 0; mi < 2; mi++) {
                    mma_f16(acc[mi][2*j],   ah[mi], b0, b1);
                    mma_f16(acc[mi][2*j+1], ah[mi], b2, b3);
                }
            }
        }
        __syncthreads();
    }

    const int row0 = m0 + wrow * 32 + (lane >> 2);
    const int colb = n0 + wcol * 64 + (lane & 3) * 2;
#pragma unroll
    for (int mi = 0; mi < 2; mi++) {
#pragma unroll
        for (int nj = 0; nj < 8; nj++) {
            int c = colb + nj * 8;
            float2 bv = *(const float2*)(bias + c);
            float o00 = acc[mi][nj][0] + bv.x, o01 = acc[mi][nj][1] + bv.y;
            float o10 = acc[mi][nj][2] + bv.x, o11 = acc[mi][nj][3] + bv.y;
            size_t r0o = (size_t)(row0 + mi * 16) * N + c;
            size_t r1o = (size_t)(row0 + mi * 16 + 8) * N + c;
            if (Ch) {
                *(uint32_t*)(Ch + r0o) = pack_hi2(o00, o01);
                *(uint32_t*)(Ch + r1o) = pack_hi2(o10, o11);
            } else {
                *(float2*)(C + r0o) = make_float2(o00, o01);
                *(float2*)(C + r1o) = make_float2(o10, o11);
            }
        }
    }
}

// ---------------------------------------------------------------------------
// Flash-attention: Q, K, V, P all single fp16 (fp32 softmax + accumulators).
// 128-row tiles, cp.async double-buffered K/V.
// ---------------------------------------------------------------------------
#define PT 72
#define AT (128 * PT)      // one tile in fp16 elems (9216)
// smem: Q | stage0 (K|V) | stage1 (K|V) = 5 tiles
#define A_SMEM (5 * AT * 2)   // 92160 B

__global__ __launch_bounds__(256) void attn_mma(
    const __half* __restrict__ ph, __half* __restrict__ oh)
{
    extern __shared__ __half sb[];
    const uint32_t uBase = smem_u32(sb);
    const uint32_t uQ = uBase;

    const int qb = gridDim.x - 1 - blockIdx.x;   // heavy blocks first
    const int bh = blockIdx.y;
    const int b = bh / HH, h = bh % HH;
    const int tid = threadIdx.x, w = tid >> 5, lane = tid & 31;
    const int quad = lane & 3, trow = lane >> 2;

    const size_t rowstride = 3 * DD;
    const size_t rbase = (size_t)b * SS * rowstride;
    const int koff = h * HD, qoff = DD + h * HD, voff = 2 * DD + h * HD;

    // Q copy: 128 rows x 8 uint4
#pragma unroll
    for (int i = tid; i < 1024; i += 256) {
        int r = i >> 3, c = i & 7;
        cp16(uBase + (r * PT + c * 8) * 2,
             ph + rbase + (size_t)(qb * 128 + r) * rowstride + qoff + c * 8);
    }

    auto load_kv = [&](int kb, int buf) {
        const uint32_t sbs = uBase + (AT + buf * 2 * AT) * 2;
#pragma unroll
        for (int i = tid; i < 2048; i += 256) {
            int t = i >> 10, idx = i & 1023;
            int r = idx >> 3, c = idx & 7;
            int off = t ? voff : koff;
            cp16(sbs + (t * AT + r * PT + c * 8) * 2,
                 ph + rbase + (size_t)(kb * 128 + r) * rowstride + off + c * 8);
        }
    };

    load_kv(0, 0);
    CP_COMMIT();

    float acc_o[8][4];
#pragma unroll
    for (int j = 0; j < 8; j++)
#pragma unroll
        for (int v = 0; v < 4; v++) acc_o[j][v] = 0.f;
    float m0 = -1e30f, m1 = -1e30f, l0 = 0.f, l1 = 0.f;

    for (int kb = 0; kb <= qb; ++kb) {
        const int buf = kb & 1;
        CP_WAIT0();
        __syncthreads();
        if (kb < qb) {
            load_kv(kb + 1, buf ^ 1);
            CP_COMMIT();
        }
        const uint32_t s0 = uBase + (AT + buf * 2 * AT) * 2;
        const uint32_t uK = s0, uV = s0 + AT * 2;

        // ---- S = Q @ K^T ----
        float s[16][4];
#pragma unroll
        for (int j = 0; j < 16; j++)
#pragma unroll
            for (int v = 0; v < 4; v++) s[j][v] = 0.f;

#pragma unroll
        for (int kc = 0; kc < 4; kc++) {
            uint32_t qf[4];
            uint32_t aoff = 2 * ((w * 16 + (lane & 15)) * PT + kc * 16 + (lane >> 4) * 8);
            ldsm_x4(qf[0], qf[1], qf[2], qf[3], uQ + aoff);
#pragma unroll
            for (int ntp = 0; ntp < 8; ntp++) {
                uint32_t boff = 2 * ((ntp * 16 + (lane & 15)) * PT + kc * 16 + (lane >> 4) * 8);
                uint32_t k0r, k1r, k2r, k3r;
                ldsm_x4(k0r, k1r, k2r, k3r, uK + boff);
                mma_f16(s[2*ntp],   qf, k0r, k2r);
                mma_f16(s[2*ntp+1], qf, k1r, k3r);
            }
        }

        // scale 1/8
#pragma unroll
        for (int nt = 0; nt < 16; nt++) {
            s[nt][0] *= 0.125f; s[nt][1] *= 0.125f;
            s[nt][2] *= 0.125f; s[nt][3] *= 0.125f;
        }

        // causal mask (diagonal block only)
        if (kb == qb) {
            const int rl0 = w * 16 + trow;
#pragma unroll
            for (int nt = 0; nt < 16; nt++) {
                int c0 = nt * 8 + 2 * quad;
                if (c0 > rl0)     s[nt][0] = -1e30f;
                if (c0 + 1 > rl0) s[nt][1] = -1e30f;
                if (c0 > rl0 + 8)     s[nt][2] = -1e30f;
                if (c0 + 1 > rl0 + 8) s[nt][3] = -1e30f;
            }
        }

        // ---- online softmax ----
        float mx0 = -1e30f, mx1 = -1e30f;
#pragma unroll
        for (int nt = 0; nt < 16; nt++) {
            mx0 = fmaxf(mx0, fmaxf(s[nt][0], s[nt][1]));
            mx1 = fmaxf(mx1, fmaxf(s[nt][2], s[nt][3]));
        }
        mx0 = fmaxf(mx0, __shfl_xor_sync(0xffffffffu, mx0, 1));
        mx0 = fmaxf(mx0, __shfl_xor_sync(0xffffffffu, mx0, 2));
        mx1 = fmaxf(mx1, __shfl_xor_sync(0xffffffffu, mx1, 1));
        mx1 = fmaxf(mx1, __shfl_xor_sync(0xffffffffu, mx1, 2));
        float m0n = fmaxf(m0, mx0), m1n = fmaxf(m1, mx1);
        float al0 = __expf(m0 - m0n), al1 = __expf(m1 - m1n);
        m0 = m0n; m1 = m1n;

        float sum0 = 0.f, sum1 = 0.f;
#pragma unroll
        for (int nt = 0; nt < 16; nt++) {
            s[nt][0] = __expf(s[nt][0] - m0); sum0 += s[nt][0];
            s[nt][1] = __expf(s[nt][1] - m0); sum0 += s[nt][1];
            s[nt][2] = __expf(s[nt][2] - m1); sum1 += s[nt][2];
            s[nt][3] = __expf(s[nt][3] - m1); sum1 += s[nt][3];
        }
        sum0 += __shfl_xor_sync(0xffffffffu, sum0, 1);
        sum0 += __shfl_xor_sync(0xffffffffu, sum0, 2);
        sum1 += __shfl_xor_sync(0xffffffffu, sum1, 1);
        sum1 += __shfl_xor_sync(0xffffffffu, sum1, 2);
        l0 = l0 * al0 + sum0;
        l1 = l1 * al1 + sum1;

#pragma unroll
        for (int j = 0; j < 8; j++) {
            acc_o[j][0] *= al0; acc_o[j][1] *= al0;
            acc_o[j][2] *= al1; acc_o[j][3] *= al1;
        }

        // ---- O += P @ V : single fp16 P ----
#pragma unroll
        for (int kc = 0; kc < 8; kc++) {
            uint32_t pha[4];
            pha[0] = pack_hi2(s[2*kc][0],   s[2*kc][1]);
            pha[1] = pack_hi2(s[2*kc][2],   s[2*kc][3]);
            pha[2] = pack_hi2(s[2*kc+1][0], s[2*kc+1][1]);
            pha[3] = pack_hi2(s[2*kc+1][2], s[2*kc+1][3]);
#pragma unroll
            for (int ht = 0; ht < 4; ht++) {
                uint32_t v0, v1, v2, v3;
                uint32_t off = 2 * ((kc * 16 + (lane & 15)) * PT + ht * 16 + (lane >> 4) * 8);
                ldsm_x4_t(v0, v1, v2, v3, uV + off);
                mma_f16(acc_o[2*ht],   pha, v0, v1);
                mma_f16(acc_o[2*ht+1], pha, v2, v3);
            }
        }
    }

    // normalize and write fp16 output
    const float inv0 = 1.f / l0, inv1 = 1.f / l1;
    const size_t grow0 = (size_t)(b * SS + qb * 128 + w * 16 + trow);
    const size_t grow1 = grow0 + 8;
#pragma unroll
    for (int j = 0; j < 8; j++) {
        int c = h * HD + j * 8 + 2 * quad;
        *(uint32_t*)(oh + grow0 * DD + c) = pack_hi2(acc_o[j][0] * inv0, acc_o[j][1] * inv0);
        *(uint32_t*)(oh + grow1 * DD + c) = pack_hi2(acc_o[j][2] * inv1, acc_o[j][3] * inv1);
    }
}

// ---------------------------------------------------------------------------
extern "C" void kernel_launch(void* const* d_in, const int* in_sizes, int n_in,
                              void* d_out, int out_size)
{
    const float* x     = (const float*)d_in[0];
    const float* W_in  = (const float*)d_in[1];
    const float* b_in  = (const float*)d_in[2];
    const float* W_out = (const float*)d_in[3];
    const float* b_out = (const float*)d_in[4];
    float* out = (float*)d_out;

    __half *x16, *w1, *w2, *ph, *ah;
    cudaGetSymbolAddress((void**)&x16, g_x16);
    cudaGetSymbolAddress((void**)&w1, g_w1);
    cudaGetSymbolAddress((void**)&w2, g_w2);
    cudaGetSymbolAddress((void**)&ph, g_ph);
    cudaGetSymbolAddress((void**)&ah, g_ah);

    const int gemm_smem = 2 * STG * (int)sizeof(__half);   // 40960
    cudaFuncSetAttribute(gemm_mma, cudaFuncAttributeMaxDynamicSharedMemorySize, gemm_smem);
    cudaFuncSetAttribute(attn_mma, cudaFuncAttributeMaxDynamicSharedMemorySize, A_SMEM);

    // prep
    conv_fp16<<<(BS * DD / 4 + 255) / 256, 256>>>(x, x16, BS * DD / 4);
    transpose_fp16<<<dim3(3 * DD / 32, DD / 32), dim3(32, 8)>>>(W_in, w1, DD, 3 * DD);
    transpose_fp16<<<dim3(DD / 32, DD / 32), dim3(32, 8)>>>(W_out, w2, DD, DD);

    // 1) QKV projection (fp16 x fp16) -> fp16 proj
    gemm_mma<<<dim3(3 * DD / 128, BS / 128), 256, gemm_smem>>>(
        x16, w1, b_in, nullptr, ph, BS, 3 * DD, DD);

    // 2) attention (all fp16 operands, fp32 softmax) -> fp16 out
    {
        dim3 grid(SS / 128, BB * HH);
        attn_mma<<<grid, 256, A_SMEM>>>(ph, ah);
    }

    // 3) output projection (fp16 x fp16) -> fp32 out
    gemm_mma<<<dim3(DD / 128, BS / 128), 256, gemm_smem>>>(
        ah, w2, b_out, out, nullptr, BS, DD, DD);
}

// round 13
// speedup vs baseline: 1.3662x; 1.0574x over previous
#include <cuda_runtime.h>
#include <cuda_fp16.h>
#include <cstdint>

// Problem constants
#define BB   4
#define SS   2048
#define DD   1024
#define HH   16
#define HD   64
#define BS   (BB*SS)        // 8192

__device__ __forceinline__ uint32_t smem_u32(const void* p) {
    uint32_t a;
    asm("{ .reg .u64 t; cvta.to.shared.u64 t, %1; cvt.u32.u64 %0, t; }" : "=r"(a) : "l"(p));
    return a;
}
__device__ __forceinline__ void cp16(uint32_t dst, const void* src) {
    asm volatile("cp.async.cg.shared.global [%0], [%1], 16;" :: "r"(dst), "l"(src));
}
#define CP_COMMIT() asm volatile("cp.async.commit_group;" ::: "memory")
#define CP_WAIT0()  asm volatile("cp.async.wait_group 0;" ::: "memory")

// ---------------------------------------------------------------------------
// Scratch (device globals)
// ---------------------------------------------------------------------------
__device__ __half g_x16[(size_t)BS * DD];      // x fp16
__device__ __half g_w1[(size_t)(3*DD) * DD];   // W_in^T  [3072,1024] fp16
__device__ __half g_w2[(size_t)DD * DD];       // W_out^T [1024,1024] fp16
__device__ __half g_ph[(size_t)BS * 3 * DD];   // proj (k|q|v) fp16
__device__ __half g_ah[(size_t)BS * DD];       // attention out fp16

// ---------------------------------------------------------------------------
// Prep kernels
// ---------------------------------------------------------------------------
__global__ __launch_bounds__(256) void conv_fp16(
    const float* __restrict__ src, __half* __restrict__ dst, int n4)
{
    int i = blockIdx.x * 256 + threadIdx.x;
    if (i >= n4) return;
    float4 v = ((const float4*)src)[i];
    ((__half2*)dst)[i*2+0] = __floats2half2_rn(v.x, v.y);
    ((__half2*)dst)[i*2+1] = __floats2half2_rn(v.z, v.w);
}

__global__ __launch_bounds__(256) void transpose_fp16(
    const float* __restrict__ W, __half* __restrict__ wt, int K, int N)
{
    __shared__ float tile[32][33];
    int k0 = blockIdx.y * 32, n0 = blockIdx.x * 32;
    int tx = threadIdx.x, ty = threadIdx.y;   // 32 x 8
#pragma unroll
    for (int j = 0; j < 32; j += 8)
        tile[ty + j][tx] = W[(size_t)(k0 + ty + j) * N + n0 + tx];
    __syncthreads();
#pragma unroll
    for (int j = 0; j < 32; j += 8)
        wt[(size_t)(n0 + ty + j) * K + k0 + tx] = __float2half_rn(tile[tx][ty + j]);
}

// ---------------------------------------------------------------------------
// mma.sync helpers
// ---------------------------------------------------------------------------
__device__ __forceinline__ void ldsm_x4(uint32_t& r0, uint32_t& r1, uint32_t& r2, uint32_t& r3,
                                        uint32_t addr) {
    asm volatile("ldmatrix.sync.aligned.m8n8.x4.shared.b16 {%0,%1,%2,%3}, [%4];"
                 : "=r"(r0), "=r"(r1), "=r"(r2), "=r"(r3) : "r"(addr));
}
__device__ __forceinline__ void ldsm_x4_t(uint32_t& r0, uint32_t& r1, uint32_t& r2, uint32_t& r3,
                                          uint32_t addr) {
    asm volatile("ldmatrix.sync.aligned.m8n8.x4.trans.shared.b16 {%0,%1,%2,%3}, [%4];"
                 : "=r"(r0), "=r"(r1), "=r"(r2), "=r"(r3) : "r"(addr));
}
__device__ __forceinline__ void mma_f16(float* d, const uint32_t* a, uint32_t b0, uint32_t b1) {
    asm volatile(
        "mma.sync.aligned.m16n8k16.row.col.f32.f16.f16.f32 "
        "{%0,%1,%2,%3}, {%4,%5,%6,%7}, {%8,%9}, {%0,%1,%2,%3};"
        : "+f"(d[0]), "+f"(d[1]), "+f"(d[2]), "+f"(d[3])
        : "r"(a[0]), "r"(a[1]), "r"(a[2]), "r"(a[3]), "r"(b0), "r"(b1));
}
__device__ __forceinline__ uint32_t pack_hi2(float x, float y) {
    __half2 t = __floats2half2_rn(x, y);
    return *(uint32_t*)&t;
}

// ---------------------------------------------------------------------------
// GEMM on mma.sync: C = A @ B^T + bias, both single fp16.
// 128x128 tile, BK=64, cp.async double buffer, 2 CTAs/SM.
// ---------------------------------------------------------------------------
#define PA 72                // pitch for 64-elem rows (+8 pad), conflict-free
#define STG (2 * 128 * PA)   // fp16 elems per stage (A | B) = 18432

__global__ __launch_bounds__(256, 2) void gemm_mma(
    const __half* __restrict__ Aa, const __half* __restrict__ Bw,
    const float* __restrict__ bias,
    float* __restrict__ C, __half* __restrict__ Ch,
    int M, int N, int K)
{
    extern __shared__ __half sg[];   // 2 * STG
    const uint32_t uBase = smem_u32(sg);

    const int tid  = threadIdx.x;
    const int wid  = tid >> 5;
    const int lane = tid & 31;
    const int wrow = wid & 3;
    const int wcol = wid >> 2;
    const int m0 = blockIdx.y * 128;
    const int n0 = blockIdx.x * 128;

    const int a_row = wrow * 32 + (lane & 7) + ((lane >> 3) & 1) * 8;
    const int a_k   = (lane >> 4) * 8;
    const int b_row = wcol * 64 + (lane >> 4) * 8 + (lane & 7);
    const int b_k   = ((lane >> 3) & 1) * 8;

    const __half* gsrc[2] = { Aa + (size_t)m0 * K, Bw + (size_t)n0 * K };

    auto load_stage = [&](int kc, int buf) {
        const int k0 = kc << 6;
        const uint32_t sb = uBase + buf * (STG * 2);
#pragma unroll
        for (int v = tid; v < 2048; v += 256) {
            int t = v >> 10, idx = v & 1023;
            int r = idx >> 3, c = idx & 7;
            cp16(sb + (t * (128 * PA) + r * PA + c * 8) * 2,
                 gsrc[t] + (size_t)r * K + k0 + c * 8);
        }
    };

    float acc[2][8][4];
#pragma unroll
    for (int i = 0; i < 2; i++)
#pragma unroll
        for (int j = 0; j < 8; j++)
#pragma unroll
            for (int v = 0; v < 4; v++) acc[i][j][v] = 0.f;

    const int nchunks = K >> 6;
    load_stage(0, 0);
    CP_COMMIT();

    for (int kc = 0; kc < nchunks; ++kc) {
        const int buf = kc & 1;
        CP_WAIT0();
        __syncthreads();
        if (kc + 1 < nchunks) {
            load_stage(kc + 1, buf ^ 1);
            CP_COMMIT();
        }
        const uint32_t s0 = uBase + buf * (STG * 2);
        const uint32_t tA = s0;
        const uint32_t tB = s0 + (128 * PA) * 2;

#pragma unroll
        for (int ks = 0; ks < 4; ks++) {
            uint32_t ah[2][4];
#pragma unroll
            for (int mi = 0; mi < 2; mi++) {
                uint32_t off = 2 * ((a_row + mi * 16) * PA + ks * 16 + a_k);
                ldsm_x4(ah[mi][0], ah[mi][1], ah[mi][2], ah[mi][3], tA + off);
            }
#pragma unroll
            for (int j = 0; j < 4; j++) {
                uint32_t off = 2 * ((b_row + j * 16) * PA + ks * 16 + b_k);
                uint32_t b0, b1, b2, b3;
                ldsm_x4(b0, b1, b2, b3, tB + off);
#pragma unroll
                for (int mi = 0; mi < 2; mi++) {
                    mma_f16(acc[mi][2*j],   ah[mi], b0, b1);
                    mma_f16(acc[mi][2*j+1], ah[mi], b2, b3);
                }
            }
        }
        __syncthreads();
    }

    const int row0 = m0 + wrow * 32 + (lane >> 2);
    const int colb = n0 + wcol * 64 + (lane & 3) * 2;
#pragma unroll
    for (int mi = 0; mi < 2; mi++) {
#pragma unroll
        for (int nj = 0; nj < 8; nj++) {
            int c = colb + nj * 8;
            float2 bv = *(const float2*)(bias + c);
            float o00 = acc[mi][nj][0] + bv.x, o01 = acc[mi][nj][1] + bv.y;
            float o10 = acc[mi][nj][2] + bv.x, o11 = acc[mi][nj][3] + bv.y;
            size_t r0o = (size_t)(row0 + mi * 16) * N + c;
            size_t r1o = (size_t)(row0 + mi * 16 + 8) * N + c;
            if (Ch) {
                *(uint32_t*)(Ch + r0o) = pack_hi2(o00, o01);
                *(uint32_t*)(Ch + r1o) = pack_hi2(o10, o11);
            } else {
                *(float2*)(C + r0o) = make_float2(o00, o01);
                *(float2*)(C + r1o) = make_float2(o10, o11);
            }
        }
    }
}

// ---------------------------------------------------------------------------
// Flash-attention: Q, K, V, P all single fp16 (fp32 softmax + accumulators).
// 128-row tiles, cp.async double-buffered K/V, 2 CTAs/SM (reg cap 128).
// ---------------------------------------------------------------------------
#define PT 72
#define AT (128 * PT)      // one tile in fp16 elems (9216)
// smem: Q | stage0 (K|V) | stage1 (K|V) = 5 tiles
#define A_SMEM (5 * AT * 2)   // 92160 B

__global__ __launch_bounds__(256, 2) void attn_mma(
    const __half* __restrict__ ph, __half* __restrict__ oh)
{
    extern __shared__ __half sb[];
    const uint32_t uBase = smem_u32(sb);
    const uint32_t uQ = uBase;

    const int qb = gridDim.x - 1 - blockIdx.x;   // heavy blocks first
    const int bh = blockIdx.y;
    const int b = bh / HH, h = bh % HH;
    const int tid = threadIdx.x, w = tid >> 5, lane = tid & 31;
    const int quad = lane & 3, trow = lane >> 2;

    const size_t rowstride = 3 * DD;
    const size_t rbase = (size_t)b * SS * rowstride;
    const int koff = h * HD, qoff = DD + h * HD, voff = 2 * DD + h * HD;

    // Q copy: 128 rows x 8 uint4
#pragma unroll
    for (int i = tid; i < 1024; i += 256) {
        int r = i >> 3, c = i & 7;
        cp16(uBase + (r * PT + c * 8) * 2,
             ph + rbase + (size_t)(qb * 128 + r) * rowstride + qoff + c * 8);
    }

    auto load_kv = [&](int kb, int buf) {
        const uint32_t sbs = uBase + (AT + buf * 2 * AT) * 2;
#pragma unroll
        for (int i = tid; i < 2048; i += 256) {
            int t = i >> 10, idx = i & 1023;
            int r = idx >> 3, c = idx & 7;
            int off = t ? voff : koff;
            cp16(sbs + (t * AT + r * PT + c * 8) * 2,
                 ph + rbase + (size_t)(kb * 128 + r) * rowstride + off + c * 8);
        }
    };

    load_kv(0, 0);
    CP_COMMIT();

    float acc_o[8][4];
#pragma unroll
    for (int j = 0; j < 8; j++)
#pragma unroll
        for (int v = 0; v < 4; v++) acc_o[j][v] = 0.f;
    float m0 = -1e30f, m1 = -1e30f, l0 = 0.f, l1 = 0.f;

    for (int kb = 0; kb <= qb; ++kb) {
        const int buf = kb & 1;
        CP_WAIT0();
        __syncthreads();
        if (kb < qb) {
            load_kv(kb + 1, buf ^ 1);
            CP_COMMIT();
        }
        const uint32_t s0 = uBase + (AT + buf * 2 * AT) * 2;
        const uint32_t uK = s0, uV = s0 + AT * 2;

        // ---- S = Q @ K^T ----
        float s[16][4];
#pragma unroll
        for (int j = 0; j < 16; j++)
#pragma unroll
            for (int v = 0; v < 4; v++) s[j][v] = 0.f;

#pragma unroll
        for (int kc = 0; kc < 4; kc++) {
            uint32_t qf[4];
            uint32_t aoff = 2 * ((w * 16 + (lane & 15)) * PT + kc * 16 + (lane >> 4) * 8);
            ldsm_x4(qf[0], qf[1], qf[2], qf[3], uQ + aoff);
#pragma unroll
            for (int ntp = 0; ntp < 8; ntp++) {
                uint32_t boff = 2 * ((ntp * 16 + (lane & 15)) * PT + kc * 16 + (lane >> 4) * 8);
                uint32_t k0r, k1r, k2r, k3r;
                ldsm_x4(k0r, k1r, k2r, k3r, uK + boff);
                mma_f16(s[2*ntp],   qf, k0r, k2r);
                mma_f16(s[2*ntp+1], qf, k1r, k3r);
            }
        }

        // scale 1/8
#pragma unroll
        for (int nt = 0; nt < 16; nt++) {
            s[nt][0] *= 0.125f; s[nt][1] *= 0.125f;
            s[nt][2] *= 0.125f; s[nt][3] *= 0.125f;
        }

        // causal mask (diagonal block only)
        if (kb == qb) {
            const int rl0 = w * 16 + trow;
#pragma unroll
            for (int nt = 0; nt < 16; nt++) {
                int c0 = nt * 8 + 2 * quad;
                if (c0 > rl0)     s[nt][0] = -1e30f;
                if (c0 + 1 > rl0) s[nt][1] = -1e30f;
                if (c0 > rl0 + 8)     s[nt][2] = -1e30f;
                if (c0 + 1 > rl0 + 8) s[nt][3] = -1e30f;
            }
        }

        // ---- online softmax ----
        float mx0 = -1e30f, mx1 = -1e30f;
#pragma unroll
        for (int nt = 0; nt < 16; nt++) {
            mx0 = fmaxf(mx0, fmaxf(s[nt][0], s[nt][1]));
            mx1 = fmaxf(mx1, fmaxf(s[nt][2], s[nt][3]));
        }
        mx0 = fmaxf(mx0, __shfl_xor_sync(0xffffffffu, mx0, 1));
        mx0 = fmaxf(mx0, __shfl_xor_sync(0xffffffffu, mx0, 2));
        mx1 = fmaxf(mx1, __shfl_xor_sync(0xffffffffu, mx1, 1));
        mx1 = fmaxf(mx1, __shfl_xor_sync(0xffffffffu, mx1, 2));
        float m0n = fmaxf(m0, mx0), m1n = fmaxf(m1, mx1);
        float al0 = __expf(m0 - m0n), al1 = __expf(m1 - m1n);
        m0 = m0n; m1 = m1n;

        float sum0 = 0.f, sum1 = 0.f;
#pragma unroll
        for (int nt = 0; nt < 16; nt++) {
            s[nt][0] = __expf(s[nt][0] - m0); sum0 += s[nt][0];
            s[nt][1] = __expf(s[nt][1] - m0); sum0 += s[nt][1];
            s[nt][2] = __expf(s[nt][2] - m1); sum1 += s[nt][2];
            s[nt][3] = __expf(s[nt][3] - m1); sum1 += s[nt][3];
        }
        sum0 += __shfl_xor_sync(0xffffffffu, sum0, 1);
        sum0 += __shfl_xor_sync(0xffffffffu, sum0, 2);
        sum1 += __shfl_xor_sync(0xffffffffu, sum1, 1);
        sum1 += __shfl_xor_sync(0xffffffffu, sum1, 2);
        l0 = l0 * al0 + sum0;
        l1 = l1 * al1 + sum1;

#pragma unroll
        for (int j = 0; j < 8; j++) {
            acc_o[j][0] *= al0; acc_o[j][1] *= al0;
            acc_o[j][2] *= al1; acc_o[j][3] *= al1;
        }

        // ---- O += P @ V : single fp16 P ----
#pragma unroll
        for (int kc = 0; kc < 8; kc++) {
            uint32_t pha[4];
            pha[0] = pack_hi2(s[2*kc][0],   s[2*kc][1]);
            pha[1] = pack_hi2(s[2*kc][2],   s[2*kc][3]);
            pha[2] = pack_hi2(s[2*kc+1][0], s[2*kc+1][1]);
            pha[3] = pack_hi2(s[2*kc+1][2], s[2*kc+1][3]);
#pragma unroll
            for (int ht = 0; ht < 4; ht++) {
                uint32_t v0, v1, v2, v3;
                uint32_t off = 2 * ((kc * 16 + (lane & 15)) * PT + ht * 16 + (lane >> 4) * 8);
                ldsm_x4_t(v0, v1, v2, v3, uV + off);
                mma_f16(acc_o[2*ht],   pha, v0, v1);
                mma_f16(acc_o[2*ht+1], pha, v2, v3);
            }
        }
    }

    // normalize and write fp16 output
    const float inv0 = 1.f / l0, inv1 = 1.f / l1;
    const size_t grow0 = (size_t)(b * SS + qb * 128 + w * 16 + trow);
    const size_t grow1 = grow0 + 8;
#pragma unroll
    for (int j = 0; j < 8; j++) {
        int c = h * HD + j * 8 + 2 * quad;
        *(uint32_t*)(oh + grow0 * DD + c) = pack_hi2(acc_o[j][0] * inv0, acc_o[j][1] * inv0);
        *(uint32_t*)(oh + grow1 * DD + c) = pack_hi2(acc_o[j][2] * inv1, acc_o[j][3] * inv1);
    }
}

// ---------------------------------------------------------------------------
extern "C" void kernel_launch(void* const* d_in, const int* in_sizes, int n_in,
                              void* d_out, int out_size)
{
    const float* x     = (const float*)d_in[0];
    const float* W_in  = (const float*)d_in[1];
    const float* b_in  = (const float*)d_in[2];
    const float* W_out = (const float*)d_in[3];
    const float* b_out = (const float*)d_in[4];
    float* out = (float*)d_out;

    __half *x16, *w1, *w2, *ph, *ah;
    cudaGetSymbolAddress((void**)&x16, g_x16);
    cudaGetSymbolAddress((void**)&w1, g_w1);
    cudaGetSymbolAddress((void**)&w2, g_w2);
    cudaGetSymbolAddress((void**)&ph, g_ph);
    cudaGetSymbolAddress((void**)&ah, g_ah);

    const int gemm_smem = 2 * STG * (int)sizeof(__half);   // 73728
    cudaFuncSetAttribute(gemm_mma, cudaFuncAttributeMaxDynamicSharedMemorySize, gemm_smem);
    cudaFuncSetAttribute(attn_mma, cudaFuncAttributeMaxDynamicSharedMemorySize, A_SMEM);

    // prep
    conv_fp16<<<(BS * DD / 4 + 255) / 256, 256>>>(x, x16, BS * DD / 4);
    transpose_fp16<<<dim3(3 * DD / 32, DD / 32), dim3(32, 8)>>>(W_in, w1, DD, 3 * DD);
    transpose_fp16<<<dim3(DD / 32, DD / 32), dim3(32, 8)>>>(W_out, w2, DD, DD);

    // 1) QKV projection (fp16 x fp16) -> fp16 proj
    gemm_mma<<<dim3(3 * DD / 128, BS / 128), 256, gemm_smem>>>(
        x16, w1, b_in, nullptr, ph, BS, 3 * DD, DD);

    // 2) attention (all fp16 operands, fp32 softmax) -> fp16 out
    {
        dim3 grid(SS / 128, BB * HH);
        attn_mma<<<grid, 256, A_SMEM>>>(ph, ah);
    }

    // 3) output projection (fp16 x fp16) -> fp32 out
    gemm_mma<<<dim3(DD / 128, BS / 128), 256, gemm_smem>>>(
        ah, w2, b_out, out, nullptr, BS, DD, DD);
}

// round 14
// speedup vs baseline: 1.4983x; 1.0967x over previous
#include <cuda_runtime.h>
#include <cuda_fp16.h>
#include <cstdint>

// Problem constants
#define BB   4
#define SS   2048
#define DD   1024
#define HH   16
#define HD   64
#define BS   (BB*SS)        // 8192

__device__ __forceinline__ uint32_t smem_u32(const void* p) {
    uint32_t a;
    asm("{ .reg .u64 t; cvta.to.shared.u64 t, %1; cvt.u32.u64 %0, t; }" : "=r"(a) : "l"(p));
    return a;
}
__device__ __forceinline__ void cp16(uint32_t dst, const void* src) {
    asm volatile("cp.async.cg.shared.global [%0], [%1], 16;" :: "r"(dst), "l"(src));
}
#define CP_COMMIT() asm volatile("cp.async.commit_group;" ::: "memory")
#define CP_WAIT0()  asm volatile("cp.async.wait_group 0;" ::: "memory")

// 0.125 * log2(e): folded into Q at the GEMM1 epilogue
#define QSCALE 0.18033688011112042f

// ---------------------------------------------------------------------------
// Scratch (device globals)
// ---------------------------------------------------------------------------
__device__ __half g_x16[(size_t)BS * DD];      // x fp16
__device__ __half g_w1[(size_t)(3*DD) * DD];   // W_in^T  [3072,1024] fp16
__device__ __half g_w2[(size_t)DD * DD];       // W_out^T [1024,1024] fp16
__device__ __half g_ph[(size_t)BS * 3 * DD];   // proj (k|q|v) fp16, q pre-scaled
__device__ __half g_ah[(size_t)BS * DD];       // attention out fp16

// ---------------------------------------------------------------------------
// Prep kernels
// ---------------------------------------------------------------------------
__global__ __launch_bounds__(256) void conv_fp16(
    const float* __restrict__ src, __half* __restrict__ dst, int n4)
{
    int i = blockIdx.x * 256 + threadIdx.x;
    if (i >= n4) return;
    float4 v = ((const float4*)src)[i];
    ((__half2*)dst)[i*2+0] = __floats2half2_rn(v.x, v.y);
    ((__half2*)dst)[i*2+1] = __floats2half2_rn(v.z, v.w);
}

__global__ __launch_bounds__(256) void transpose_fp16(
    const float* __restrict__ W, __half* __restrict__ wt, int K, int N)
{
    __shared__ float tile[32][33];
    int k0 = blockIdx.y * 32, n0 = blockIdx.x * 32;
    int tx = threadIdx.x, ty = threadIdx.y;   // 32 x 8
#pragma unroll
    for (int j = 0; j < 32; j += 8)
        tile[ty + j][tx] = W[(size_t)(k0 + ty + j) * N + n0 + tx];
    __syncthreads();
#pragma unroll
    for (int j = 0; j < 32; j += 8)
        wt[(size_t)(n0 + ty + j) * K + k0 + tx] = __float2half_rn(tile[tx][ty + j]);
}

// ---------------------------------------------------------------------------
// mma.sync helpers
// ---------------------------------------------------------------------------
__device__ __forceinline__ void ldsm_x4(uint32_t& r0, uint32_t& r1, uint32_t& r2, uint32_t& r3,
                                        uint32_t addr) {
    asm volatile("ldmatrix.sync.aligned.m8n8.x4.shared.b16 {%0,%1,%2,%3}, [%4];"
                 : "=r"(r0), "=r"(r1), "=r"(r2), "=r"(r3) : "r"(addr));
}
__device__ __forceinline__ void ldsm_x4_t(uint32_t& r0, uint32_t& r1, uint32_t& r2, uint32_t& r3,
                                          uint32_t addr) {
    asm volatile("ldmatrix.sync.aligned.m8n8.x4.trans.shared.b16 {%0,%1,%2,%3}, [%4];"
                 : "=r"(r0), "=r"(r1), "=r"(r2), "=r"(r3) : "r"(addr));
}
__device__ __forceinline__ void mma_f16(float* d, const uint32_t* a, uint32_t b0, uint32_t b1) {
    asm volatile(
        "mma.sync.aligned.m16n8k16.row.col.f32.f16.f16.f32 "
        "{%0,%1,%2,%3}, {%4,%5,%6,%7}, {%8,%9}, {%0,%1,%2,%3};"
        : "+f"(d[0]), "+f"(d[1]), "+f"(d[2]), "+f"(d[3])
        : "r"(a[0]), "r"(a[1]), "r"(a[2]), "r"(a[3]), "r"(b0), "r"(b1));
}
__device__ __forceinline__ uint32_t pack_hi2(float x, float y) {
    __half2 t = __floats2half2_rn(x, y);
    return *(uint32_t*)&t;
}
__device__ __forceinline__ float ex2f(float x) {
    float r;
    asm("ex2.approx.f32 %0, %1;" : "=f"(r) : "f"(x));
    return r;
}

// ---------------------------------------------------------------------------
// GEMM on mma.sync: C = A @ B^T + bias, both single fp16.
// 128x128 tile, BK=64, cp.async double buffer, 2 CTAs/SM, single sync/chunk.
// When writing Ch (fp16), columns in [DD, 2DD) are scaled by QSCALE (Q cols).
// ---------------------------------------------------------------------------
#define PA 72                // pitch for 64-elem rows (+8 pad), conflict-free
#define STG (2 * 128 * PA)   // fp16 elems per stage (A | B) = 18432

__global__ __launch_bounds__(256, 2) void gemm_mma(
    const __half* __restrict__ Aa, const __half* __restrict__ Bw,
    const float* __restrict__ bias,
    float* __restrict__ C, __half* __restrict__ Ch,
    int M, int N, int K)
{
    extern __shared__ __half sg[];   // 2 * STG
    const uint32_t uBase = smem_u32(sg);

    const int tid  = threadIdx.x;
    const int wid  = tid >> 5;
    const int lane = tid & 31;
    const int wrow = wid & 3;
    const int wcol = wid >> 2;
    const int m0 = blockIdx.y * 128;
    const int n0 = blockIdx.x * 128;

    const int a_row = wrow * 32 + (lane & 7) + ((lane >> 3) & 1) * 8;
    const int a_k   = (lane >> 4) * 8;
    const int b_row = wcol * 64 + (lane >> 4) * 8 + (lane & 7);
    const int b_k   = ((lane >> 3) & 1) * 8;

    const __half* gsrc[2] = { Aa + (size_t)m0 * K, Bw + (size_t)n0 * K };

    auto load_stage = [&](int kc, int buf) {
        const int k0 = kc << 6;
        const uint32_t sb = uBase + buf * (STG * 2);
#pragma unroll
        for (int v = tid; v < 2048; v += 256) {
            int t = v >> 10, idx = v & 1023;
            int r = idx >> 3, c = idx & 7;
            cp16(sb + (t * (128 * PA) + r * PA + c * 8) * 2,
                 gsrc[t] + (size_t)r * K + k0 + c * 8);
        }
    };

    float acc[2][8][4];
#pragma unroll
    for (int i = 0; i < 2; i++)
#pragma unroll
        for (int j = 0; j < 8; j++)
#pragma unroll
            for (int v = 0; v < 4; v++) acc[i][j][v] = 0.f;

    const int nchunks = K >> 6;
    load_stage(0, 0);
    CP_COMMIT();

    for (int kc = 0; kc < nchunks; ++kc) {
        const int buf = kc & 1;
        CP_WAIT0();
        __syncthreads();   // orders: prev reads done + this chunk's data visible
        if (kc + 1 < nchunks) {
            load_stage(kc + 1, buf ^ 1);
            CP_COMMIT();
        }
        const uint32_t s0 = uBase + buf * (STG * 2);
        const uint32_t tA = s0;
        const uint32_t tB = s0 + (128 * PA) * 2;

#pragma unroll
        for (int ks = 0; ks < 4; ks++) {
            uint32_t ah[2][4];
#pragma unroll
            for (int mi = 0; mi < 2; mi++) {
                uint32_t off = 2 * ((a_row + mi * 16) * PA + ks * 16 + a_k);
                ldsm_x4(ah[mi][0], ah[mi][1], ah[mi][2], ah[mi][3], tA + off);
            }
#pragma unroll
            for (int j = 0; j < 4; j++) {
                uint32_t off = 2 * ((b_row + j * 16) * PA + ks * 16 + b_k);
                uint32_t b0, b1, b2, b3;
                ldsm_x4(b0, b1, b2, b3, tB + off);
#pragma unroll
                for (int mi = 0; mi < 2; mi++) {
                    mma_f16(acc[mi][2*j],   ah[mi], b0, b1);
                    mma_f16(acc[mi][2*j+1], ah[mi], b2, b3);
                }
            }
        }
    }

    // epilogue; Q-columns pre-scaled by QSCALE when writing fp16 proj
    const float qs = (Ch && n0 >= DD && n0 < 2 * DD) ? QSCALE : 1.0f;
    const int row0 = m0 + wrow * 32 + (lane >> 2);
    const int colb = n0 + wcol * 64 + (lane & 3) * 2;
#pragma unroll
    for (int mi = 0; mi < 2; mi++) {
#pragma unroll
        for (int nj = 0; nj < 8; nj++) {
            int c = colb + nj * 8;
            float2 bv = *(const float2*)(bias + c);
            float o00 = (acc[mi][nj][0] + bv.x) * qs, o01 = (acc[mi][nj][1] + bv.y) * qs;
            float o10 = (acc[mi][nj][2] + bv.x) * qs, o11 = (acc[mi][nj][3] + bv.y) * qs;
            size_t r0o = (size_t)(row0 + mi * 16) * N + c;
            size_t r1o = (size_t)(row0 + mi * 16 + 8) * N + c;
            if (Ch) {
                *(uint32_t*)(Ch + r0o) = pack_hi2(o00, o01);
                *(uint32_t*)(Ch + r1o) = pack_hi2(o10, o11);
            } else {
                *(float2*)(C + r0o) = make_float2(o00, o01);
                *(float2*)(C + r1o) = make_float2(o10, o11);
            }
        }
    }
}

// ---------------------------------------------------------------------------
// Flash-attention, max-free softmax:
//   Q pre-scaled by 0.125*log2e -> p = 2^s (ex2.approx), unnormalized.
//   l computed by ones-column MMA (consistent with fp16 numerator).
// Q/K/V/P single fp16, fp32 accumulators. 2 CTAs/SM.
// ---------------------------------------------------------------------------
#define PT 72
#define AT (128 * PT)      // one tile in fp16 elems (9216)
#define A_SMEM (5 * AT * 2)   // Q | 2 stages of (K|V) = 92160 B
#define ONES2 0x3C003C00u     // half2(1,1)

__global__ __launch_bounds__(256, 2) void attn_mma(
    const __half* __restrict__ ph, __half* __restrict__ oh)
{
    extern __shared__ __half sb[];
    const uint32_t uBase = smem_u32(sb);
    const uint32_t uQ = uBase;

    const int qb = gridDim.x - 1 - blockIdx.x;   // heavy blocks first
    const int bh = blockIdx.y;
    const int b = bh / HH, h = bh % HH;
    const int tid = threadIdx.x, w = tid >> 5, lane = tid & 31;
    const int quad = lane & 3, trow = lane >> 2;

    const size_t rowstride = 3 * DD;
    const size_t rbase = (size_t)b * SS * rowstride;
    const int koff = h * HD, qoff = DD + h * HD, voff = 2 * DD + h * HD;

    // Q copy: 128 rows x 8 uint4
#pragma unroll
    for (int i = tid; i < 1024; i += 256) {
        int r = i >> 3, c = i & 7;
        cp16(uBase + (r * PT + c * 8) * 2,
             ph + rbase + (size_t)(qb * 128 + r) * rowstride + qoff + c * 8);
    }

    auto load_kv = [&](int kb, int buf) {
        const uint32_t sbs = uBase + (AT + buf * 2 * AT) * 2;
#pragma unroll
        for (int i = tid; i < 2048; i += 256) {
            int t = i >> 10, idx = i & 1023;
            int r = idx >> 3, c = idx & 7;
            int off = t ? voff : koff;
            cp16(sbs + (t * AT + r * PT + c * 8) * 2,
                 ph + rbase + (size_t)(kb * 128 + r) * rowstride + off + c * 8);
        }
    };

    load_kv(0, 0);
    CP_COMMIT();

    float acc_o[8][4];
#pragma unroll
    for (int j = 0; j < 8; j++)
#pragma unroll
        for (int v = 0; v < 4; v++) acc_o[j][v] = 0.f;
    float acc_l[4] = {0.f, 0.f, 0.f, 0.f};   // l via ones-MMA

    for (int kb = 0; kb <= qb; ++kb) {
        const int buf = kb & 1;
        CP_WAIT0();
        __syncthreads();
        if (kb < qb) {
            load_kv(kb + 1, buf ^ 1);
            CP_COMMIT();
        }
        const uint32_t s0 = uBase + (AT + buf * 2 * AT) * 2;
        const uint32_t uK = s0, uV = s0 + AT * 2;

        // ---- S = Q' @ K^T (Q pre-scaled) ----
        float s[16][4];
#pragma unroll
        for (int j = 0; j < 16; j++)
#pragma unroll
            for (int v = 0; v < 4; v++) s[j][v] = 0.f;

#pragma unroll
        for (int kc = 0; kc < 4; kc++) {
            uint32_t qf[4];
            uint32_t aoff = 2 * ((w * 16 + (lane & 15)) * PT + kc * 16 + (lane >> 4) * 8);
            ldsm_x4(qf[0], qf[1], qf[2], qf[3], uQ + aoff);
#pragma unroll
            for (int ntp = 0; ntp < 8; ntp++) {
                uint32_t boff = 2 * ((ntp * 16 + (lane & 15)) * PT + kc * 16 + (lane >> 4) * 8);
                uint32_t k0r, k1r, k2r, k3r;
                ldsm_x4(k0r, k1r, k2r, k3r, uK + boff);
                mma_f16(s[2*ntp],   qf, k0r, k2r);
                mma_f16(s[2*ntp+1], qf, k1r, k3r);
            }
        }

        // causal mask (diagonal block only)
        if (kb == qb) {
            const int rl0 = w * 16 + trow;
#pragma unroll
            for (int nt = 0; nt < 16; nt++) {
                int c0 = nt * 8 + 2 * quad;
                if (c0 > rl0)     s[nt][0] = -1e30f;
                if (c0 + 1 > rl0) s[nt][1] = -1e30f;
                if (c0 > rl0 + 8)     s[nt][2] = -1e30f;
                if (c0 + 1 > rl0 + 8) s[nt][3] = -1e30f;
            }
        }

        // ---- p = 2^s ; O += P@V ; l += P@ones — all fused per k-chunk ----
#pragma unroll
        for (int kc = 0; kc < 8; kc++) {
            uint32_t pha[4];
            pha[0] = pack_hi2(ex2f(s[2*kc][0]),   ex2f(s[2*kc][1]));
            pha[1] = pack_hi2(ex2f(s[2*kc][2]),   ex2f(s[2*kc][3]));
            pha[2] = pack_hi2(ex2f(s[2*kc+1][0]), ex2f(s[2*kc+1][1]));
            pha[3] = pack_hi2(ex2f(s[2*kc+1][2]), ex2f(s[2*kc+1][3]));
            mma_f16(acc_l, pha, ONES2, ONES2);   // row sums on tensor pipe
#pragma unroll
            for (int ht = 0; ht < 4; ht++) {
                uint32_t v0, v1, v2, v3;
                uint32_t off = 2 * ((kc * 16 + (lane & 15)) * PT + ht * 16 + (lane >> 4) * 8);
                ldsm_x4_t(v0, v1, v2, v3, uV + off);
                mma_f16(acc_o[2*ht],   pha, v0, v1);
                mma_f16(acc_o[2*ht+1], pha, v2, v3);
            }
        }
    }

    // normalize and write fp16 output
    const float inv0 = 1.f / acc_l[0], inv1 = 1.f / acc_l[2];
    const size_t grow0 = (size_t)(b * SS + qb * 128 + w * 16 + trow);
    const size_t grow1 = grow0 + 8;
#pragma unroll
    for (int j = 0; j < 8; j++) {
        int c = h * HD + j * 8 + 2 * quad;
        *(uint32_t*)(oh + grow0 * DD + c) = pack_hi2(acc_o[j][0] * inv0, acc_o[j][1] * inv0);
        *(uint32_t*)(oh + grow1 * DD + c) = pack_hi2(acc_o[j][2] * inv1, acc_o[j][3] * inv1);
    }
}

// ---------------------------------------------------------------------------
extern "C" void kernel_launch(void* const* d_in, const int* in_sizes, int n_in,
                              void* d_out, int out_size)
{
    const float* x     = (const float*)d_in[0];
    const float* W_in  = (const float*)d_in[1];
    const float* b_in  = (const float*)d_in[2];
    const float* W_out = (const float*)d_in[3];
    const float* b_out = (const float*)d_in[4];
    float* out = (float*)d_out;

    __half *x16, *w1, *w2, *ph, *ah;
    cudaGetSymbolAddress((void**)&x16, g_x16);
    cudaGetSymbolAddress((void**)&w1, g_w1);
    cudaGetSymbolAddress((void**)&w2, g_w2);
    cudaGetSymbolAddress((void**)&ph, g_ph);
    cudaGetSymbolAddress((void**)&ah, g_ah);

    const int gemm_smem = 2 * STG * (int)sizeof(__half);   // 73728
    cudaFuncSetAttribute(gemm_mma, cudaFuncAttributeMaxDynamicSharedMemorySize, gemm_smem);
    cudaFuncSetAttribute(attn_mma, cudaFuncAttributeMaxDynamicSharedMemorySize, A_SMEM);

    // prep
    conv_fp16<<<(BS * DD / 4 + 255) / 256, 256>>>(x, x16, BS * DD / 4);
    transpose_fp16<<<dim3(3 * DD / 32, DD / 32), dim3(32, 8)>>>(W_in, w1, DD, 3 * DD);
    transpose_fp16<<<dim3(DD / 32, DD / 32), dim3(32, 8)>>>(W_out, w2, DD, DD);

    // 1) QKV projection (fp16 x fp16) -> fp16 proj (Q columns pre-scaled)
    gemm_mma<<<dim3(3 * DD / 128, BS / 128), 256, gemm_smem>>>(
        x16, w1, b_in, nullptr, ph, BS, 3 * DD, DD);

    // 2) attention (max-free softmax, l via ones-MMA) -> fp16 out
    {
        dim3 grid(SS / 128, BB * HH);
        attn_mma<<<grid, 256, A_SMEM>>>(ph, ah);
    }

    // 3) output projection (fp16 x fp16) -> fp32 out
    gemm_mma<<<dim3(DD / 128, BS / 128), 256, gemm_smem>>>(
        ah, w2, b_out, out, nullptr, BS, DD, DD);
}

// round 15
// speedup vs baseline: 1.5404x; 1.0281x over previous
#include <cuda_runtime.h>
#include <cuda_fp16.h>
#include <cstdint>

// Problem constants
#define BB   4
#define SS   2048
#define DD   1024
#define HH   16
#define HD   64
#define BS   (BB*SS)        // 8192

__device__ __forceinline__ uint32_t smem_u32(const void* p) {
    uint32_t a;
    asm("{ .reg .u64 t; cvta.to.shared.u64 t, %1; cvt.u32.u64 %0, t; }" : "=r"(a) : "l"(p));
    return a;
}
__device__ __forceinline__ void cp16(uint32_t dst, const void* src) {
    asm volatile("cp.async.cg.shared.global [%0], [%1], 16;" :: "r"(dst), "l"(src));
}
#define CP_COMMIT() asm volatile("cp.async.commit_group;" ::: "memory")
#define CP_WAIT0()  asm volatile("cp.async.wait_group 0;" ::: "memory")

// 0.125 * log2(e): folded into Q at the GEMM1 epilogue
#define QSCALE 0.18033688011112042f

// ---------------------------------------------------------------------------
// Scratch (device globals)
// ---------------------------------------------------------------------------
__device__ __half g_x16[(size_t)BS * DD];      // x fp16
__device__ __half g_w1[(size_t)DD * (3*DD)];   // W_in  [1024,3072] fp16 (row-major, NO transpose)
__device__ __half g_w2[(size_t)DD * DD];       // W_out [1024,1024] fp16 (row-major)
__device__ __half g_ph[(size_t)BS * 3 * DD];   // proj (k|q|v) fp16, q pre-scaled
__device__ __half g_ah[(size_t)BS * DD];       // attention out fp16

// ---------------------------------------------------------------------------
// Fused prep: convert x, W_in, W_out to fp16 in one launch.
// ---------------------------------------------------------------------------
#define N4X  (BS * DD / 4)              // 2097152
#define N4W1 (DD * 3 * DD / 4)          // 786432
#define N4W2 (DD * DD / 4)              // 262144
#define N4ALL (N4X + N4W1 + N4W2)       // 3145728

__global__ __launch_bounds__(256) void conv_all(
    const float* __restrict__ x, const float* __restrict__ W1,
    const float* __restrict__ W2,
    __half* __restrict__ x16, __half* __restrict__ w1, __half* __restrict__ w2)
{
    int i = blockIdx.x * 256 + threadIdx.x;
    if (i >= N4ALL) return;
    const float* src;
    __half* dst;
    int j;
    if (i < N4X)              { src = x;  dst = x16; j = i; }
    else if (i < N4X + N4W1)  { src = W1; dst = w1;  j = i - N4X; }
    else                      { src = W2; dst = w2;  j = i - N4X - N4W1; }
    float4 v = ((const float4*)src)[j];
    ((__half2*)dst)[j*2+0] = __floats2half2_rn(v.x, v.y);
    ((__half2*)dst)[j*2+1] = __floats2half2_rn(v.z, v.w);
}

// ---------------------------------------------------------------------------
// mma.sync helpers
// ---------------------------------------------------------------------------
__device__ __forceinline__ void ldsm_x4(uint32_t& r0, uint32_t& r1, uint32_t& r2, uint32_t& r3,
                                        uint32_t addr) {
    asm volatile("ldmatrix.sync.aligned.m8n8.x4.shared.b16 {%0,%1,%2,%3}, [%4];"
                 : "=r"(r0), "=r"(r1), "=r"(r2), "=r"(r3) : "r"(addr));
}
__device__ __forceinline__ void ldsm_x4_t(uint32_t& r0, uint32_t& r1, uint32_t& r2, uint32_t& r3,
                                          uint32_t addr) {
    asm volatile("ldmatrix.sync.aligned.m8n8.x4.trans.shared.b16 {%0,%1,%2,%3}, [%4];"
                 : "=r"(r0), "=r"(r1), "=r"(r2), "=r"(r3) : "r"(addr));
}
__device__ __forceinline__ void mma_f16(float* d, const uint32_t* a, uint32_t b0, uint32_t b1) {
    asm volatile(
        "mma.sync.aligned.m16n8k16.row.col.f32.f16.f16.f32 "
        "{%0,%1,%2,%3}, {%4,%5,%6,%7}, {%8,%9}, {%0,%1,%2,%3};"
        : "+f"(d[0]), "+f"(d[1]), "+f"(d[2]), "+f"(d[3])
        : "r"(a[0]), "r"(a[1]), "r"(a[2]), "r"(a[3]), "r"(b0), "r"(b1));
}
__device__ __forceinline__ uint32_t pack_hi2(float x, float y) {
    __half2 t = __floats2half2_rn(x, y);
    return *(uint32_t*)&t;
}
__device__ __forceinline__ float ex2f(float x) {
    float r;
    asm("ex2.approx.f32 %0, %1;" : "=f"(r) : "f"(x));
    return r;
}

// ---------------------------------------------------------------------------
// GEMM on mma.sync: C = A @ B + bias; A [M,K] fp16, B [K,N] fp16 (row-major,
// consumed via ldsm.trans — no weight transpose needed).
// 128x128 tile, BK=64, cp.async double buffer, 2 CTAs/SM.
// When writing Ch (fp16), columns in [DD, 2DD) are scaled by QSCALE (Q cols).
// ---------------------------------------------------------------------------
#define PA 72                 // A tile pitch: 128 rows(m) x 64 cols(k), +8 pad
#define PB 136                // B tile pitch: 64 rows(k) x 128 cols(n), +8 pad
#define ASZA (128 * PA)       // 9216 halfs
#define BSZB (64 * PB)        // 8704 halfs
#define STG (ASZA + BSZB)     // 17920 halfs per stage

__global__ __launch_bounds__(256, 2) void gemm_mma(
    const __half* __restrict__ Aa, const __half* __restrict__ Bw,
    const float* __restrict__ bias,
    float* __restrict__ C, __half* __restrict__ Ch,
    int M, int N, int K)
{
    extern __shared__ __half sg[];   // 2 * STG
    const uint32_t uBase = smem_u32(sg);

    const int tid  = threadIdx.x;
    const int wid  = tid >> 5;
    const int lane = tid & 31;
    const int wrow = wid & 3;
    const int wcol = wid >> 2;
    const int m0 = blockIdx.y * 128;
    const int n0 = blockIdx.x * 128;

    const int a_row = wrow * 32 + (lane & 7) + ((lane >> 3) & 1) * 8;
    const int a_k   = (lane >> 4) * 8;
    // B fragment lane addressing (ldsm.trans from [k,n] tile):
    const int b_kr  = lane & 15;            // k row within 16
    const int b_nc  = (lane >> 4) * 8;      // n col offset within 16

    const __half* gA = Aa + (size_t)m0 * K;

    auto load_stage = [&](int kc, int buf) {
        const int k0 = kc << 6;
        const uint32_t sb = uBase + buf * (STG * 2);
        const __half* gAk = gA + k0;
        const __half* gB  = Bw + (size_t)k0 * N + n0;
#pragma unroll
        for (int v = tid; v < 2048; v += 256) {
            if (v < 1024) {
                int r = v >> 3, c = v & 7;                 // A: 128 rows x 8 vec
                cp16(sb + (r * PA + c * 8) * 2, gAk + (size_t)r * K + c * 8);
            } else {
                int idx = v - 1024;
                int r = idx >> 4, c = idx & 15;            // B: 64 rows x 16 vec
                cp16(sb + (ASZA + r * PB + c * 8) * 2, gB + (size_t)r * N + c * 8);
            }
        }
    };

    float acc[2][8][4];
#pragma unroll
    for (int i = 0; i < 2; i++)
#pragma unroll
        for (int j = 0; j < 8; j++)
#pragma unroll
            for (int v = 0; v < 4; v++) acc[i][j][v] = 0.f;

    const int nchunks = K >> 6;
    load_stage(0, 0);
    CP_COMMIT();

    for (int kc = 0; kc < nchunks; ++kc) {
        const int buf = kc & 1;
        CP_WAIT0();
        __syncthreads();
        if (kc + 1 < nchunks) {
            load_stage(kc + 1, buf ^ 1);
            CP_COMMIT();
        }
        const uint32_t s0 = uBase + buf * (STG * 2);
        const uint32_t tA = s0;
        const uint32_t tB = s0 + ASZA * 2;

#pragma unroll
        for (int ks = 0; ks < 4; ks++) {
            uint32_t ah[2][4];
#pragma unroll
            for (int mi = 0; mi < 2; mi++) {
                uint32_t off = 2 * ((a_row + mi * 16) * PA + ks * 16 + a_k);
                ldsm_x4(ah[mi][0], ah[mi][1], ah[mi][2], ah[mi][3], tA + off);
            }
#pragma unroll
            for (int j = 0; j < 4; j++) {
                // trans-load from [k,n]: row = k, col = n  (proven pattern from attn PV)
                uint32_t off = 2 * ((ks * 16 + b_kr) * PB + wcol * 64 + j * 16 + b_nc);
                uint32_t b0, b1, b2, b3;
                ldsm_x4_t(b0, b1, b2, b3, tB + off);
#pragma unroll
                for (int mi = 0; mi < 2; mi++) {
                    mma_f16(acc[mi][2*j],   ah[mi], b0, b1);
                    mma_f16(acc[mi][2*j+1], ah[mi], b2, b3);
                }
            }
        }
    }

    // epilogue; Q-columns pre-scaled by QSCALE when writing fp16 proj
    const float qs = (Ch && n0 >= DD && n0 < 2 * DD) ? QSCALE : 1.0f;
    const int row0 = m0 + wrow * 32 + (lane >> 2);
    const int colb = n0 + wcol * 64 + (lane & 3) * 2;
#pragma unroll
    for (int mi = 0; mi < 2; mi++) {
#pragma unroll
        for (int nj = 0; nj < 8; nj++) {
            int c = colb + nj * 8;
            float2 bv = *(const float2*)(bias + c);
            float o00 = (acc[mi][nj][0] + bv.x) * qs, o01 = (acc[mi][nj][1] + bv.y) * qs;
            float o10 = (acc[mi][nj][2] + bv.x) * qs, o11 = (acc[mi][nj][3] + bv.y) * qs;
            size_t r0o = (size_t)(row0 + mi * 16) * N + c;
            size_t r1o = (size_t)(row0 + mi * 16 + 8) * N + c;
            if (Ch) {
                *(uint32_t*)(Ch + r0o) = pack_hi2(o00, o01);
                *(uint32_t*)(Ch + r1o) = pack_hi2(o10, o11);
            } else {
                *(float2*)(C + r0o) = make_float2(o00, o01);
                *(float2*)(C + r1o) = make_float2(o10, o11);
            }
        }
    }
}

// ---------------------------------------------------------------------------
// Flash-attention, max-free softmax (unchanged from R14):
//   Q pre-scaled by 0.125*log2e -> p = 2^s (ex2.approx), unnormalized.
//   l computed by ones-column MMA. Q/K/V/P single fp16. 2 CTAs/SM.
// ---------------------------------------------------------------------------
#define PT 72
#define AT (128 * PT)         // one tile in fp16 elems (9216)
#define A_SMEM (5 * AT * 2)   // Q | 2 stages of (K|V) = 92160 B
#define ONES2 0x3C003C00u     // half2(1,1)

__global__ __launch_bounds__(256, 2) void attn_mma(
    const __half* __restrict__ ph, __half* __restrict__ oh)
{
    extern __shared__ __half sb[];
    const uint32_t uBase = smem_u32(sb);
    const uint32_t uQ = uBase;

    const int qb = gridDim.x - 1 - blockIdx.x;   // heavy blocks first
    const int bh = blockIdx.y;
    const int b = bh / HH, h = bh % HH;
    const int tid = threadIdx.x, w = tid >> 5, lane = tid & 31;
    const int quad = lane & 3, trow = lane >> 2;

    const size_t rowstride = 3 * DD;
    const size_t rbase = (size_t)b * SS * rowstride;
    const int koff = h * HD, qoff = DD + h * HD, voff = 2 * DD + h * HD;

    // Q copy: 128 rows x 8 uint4
#pragma unroll
    for (int i = tid; i < 1024; i += 256) {
        int r = i >> 3, c = i & 7;
        cp16(uBase + (r * PT + c * 8) * 2,
             ph + rbase + (size_t)(qb * 128 + r) * rowstride + qoff + c * 8);
    }

    auto load_kv = [&](int kb, int buf) {
        const uint32_t sbs = uBase + (AT + buf * 2 * AT) * 2;
#pragma unroll
        for (int i = tid; i < 2048; i += 256) {
            int t = i >> 10, idx = i & 1023;
            int r = idx >> 3, c = idx & 7;
            int off = t ? voff : koff;
            cp16(sbs + (t * AT + r * PT + c * 8) * 2,
                 ph + rbase + (size_t)(kb * 128 + r) * rowstride + off + c * 8);
        }
    };

    load_kv(0, 0);
    CP_COMMIT();

    float acc_o[8][4];
#pragma unroll
    for (int j = 0; j < 8; j++)
#pragma unroll
        for (int v = 0; v < 4; v++) acc_o[j][v] = 0.f;
    float acc_l[4] = {0.f, 0.f, 0.f, 0.f};   // l via ones-MMA

    for (int kb = 0; kb <= qb; ++kb) {
        const int buf = kb & 1;
        CP_WAIT0();
        __syncthreads();
        if (kb < qb) {
            load_kv(kb + 1, buf ^ 1);
            CP_COMMIT();
        }
        const uint32_t s0 = uBase + (AT + buf * 2 * AT) * 2;
        const uint32_t uK = s0, uV = s0 + AT * 2;

        // ---- S = Q' @ K^T (Q pre-scaled) ----
        float s[16][4];
#pragma unroll
        for (int j = 0; j < 16; j++)
#pragma unroll
            for (int v = 0; v < 4; v++) s[j][v] = 0.f;

#pragma unroll
        for (int kc = 0; kc < 4; kc++) {
            uint32_t qf[4];
            uint32_t aoff = 2 * ((w * 16 + (lane & 15)) * PT + kc * 16 + (lane >> 4) * 8);
            ldsm_x4(qf[0], qf[1], qf[2], qf[3], uQ + aoff);
#pragma unroll
            for (int ntp = 0; ntp < 8; ntp++) {
                uint32_t boff = 2 * ((ntp * 16 + (lane & 15)) * PT + kc * 16 + (lane >> 4) * 8);
                uint32_t k0r, k1r, k2r, k3r;
                ldsm_x4(k0r, k1r, k2r, k3r, uK + boff);
                mma_f16(s[2*ntp],   qf, k0r, k2r);
                mma_f16(s[2*ntp+1], qf, k1r, k3r);
            }
        }

        // causal mask (diagonal block only)
        if (kb == qb) {
            const int rl0 = w * 16 + trow;
#pragma unroll
            for (int nt = 0; nt < 16; nt++) {
                int c0 = nt * 8 + 2 * quad;
                if (c0 > rl0)     s[nt][0] = -1e30f;
                if (c0 + 1 > rl0) s[nt][1] = -1e30f;
                if (c0 > rl0 + 8)     s[nt][2] = -1e30f;
                if (c0 + 1 > rl0 + 8) s[nt][3] = -1e30f;
            }
        }

        // ---- p = 2^s ; O += P@V ; l += P@ones — fused per k-chunk ----
#pragma unroll
        for (int kc = 0; kc < 8; kc++) {
            uint32_t pha[4];
            pha[0] = pack_hi2(ex2f(s[2*kc][0]),   ex2f(s[2*kc][1]));
            pha[1] = pack_hi2(ex2f(s[2*kc][2]),   ex2f(s[2*kc][3]));
            pha[2] = pack_hi2(ex2f(s[2*kc+1][0]), ex2f(s[2*kc+1][1]));
            pha[3] = pack_hi2(ex2f(s[2*kc+1][2]), ex2f(s[2*kc+1][3]));
            mma_f16(acc_l, pha, ONES2, ONES2);   // row sums on tensor pipe
#pragma unroll
            for (int ht = 0; ht < 4; ht++) {
                uint32_t v0, v1, v2, v3;
                uint32_t off = 2 * ((kc * 16 + (lane & 15)) * PT + ht * 16 + (lane >> 4) * 8);
                ldsm_x4_t(v0, v1, v2, v3, uV + off);
                mma_f16(acc_o[2*ht],   pha, v0, v1);
                mma_f16(acc_o[2*ht+1], pha, v2, v3);
            }
        }
    }

    // normalize and write fp16 output
    const float inv0 = 1.f / acc_l[0], inv1 = 1.f / acc_l[2];
    const size_t grow0 = (size_t)(b * SS + qb * 128 + w * 16 + trow);
    const size_t grow1 = grow0 + 8;
#pragma unroll
    for (int j = 0; j < 8; j++) {
        int c = h * HD + j * 8 + 2 * quad;
        *(uint32_t*)(oh + grow0 * DD + c) = pack_hi2(acc_o[j][0] * inv0, acc_o[j][1] * inv0);
        *(uint32_t*)(oh + grow1 * DD + c) = pack_hi2(acc_o[j][2] * inv1, acc_o[j][3] * inv1);
    }
}

// ---------------------------------------------------------------------------
extern "C" void kernel_launch(void* const* d_in, const int* in_sizes, int n_in,
                              void* d_out, int out_size)
{
    const float* x     = (const float*)d_in[0];
    const float* W_in  = (const float*)d_in[1];
    const float* b_in  = (const float*)d_in[2];
    const float* W_out = (const float*)d_in[3];
    const float* b_out = (const float*)d_in[4];
    float* out = (float*)d_out;

    __half *x16, *w1, *w2, *ph, *ah;
    cudaGetSymbolAddress((void**)&x16, g_x16);
    cudaGetSymbolAddress((void**)&w1, g_w1);
    cudaGetSymbolAddress((void**)&w2, g_w2);
    cudaGetSymbolAddress((void**)&ph, g_ph);
    cudaGetSymbolAddress((void**)&ah, g_ah);

    const int gemm_smem = 2 * STG * (int)sizeof(__half);   // 71680
    cudaFuncSetAttribute(gemm_mma, cudaFuncAttributeMaxDynamicSharedMemorySize, gemm_smem);
    cudaFuncSetAttribute(attn_mma, cudaFuncAttributeMaxDynamicSharedMemorySize, A_SMEM);

    // fused prep: x, W_in, W_out -> fp16 (no transposes)
    conv_all<<<(N4ALL + 255) / 256, 256>>>(x, W_in, W_out, x16, w1, w2);

    // 1) QKV projection (A[M,K] x B[K,N]) -> fp16 proj (Q columns pre-scaled)
    gemm_mma<<<dim3(3 * DD / 128, BS / 128), 256, gemm_smem>>>(
        x16, w1, b_in, nullptr, ph, BS, 3 * DD, DD);

    // 2) attention (max-free softmax, l via ones-MMA) -> fp16 out
    {
        dim3 grid(SS / 128, BB * HH);
        attn_mma<<<grid, 256, A_SMEM>>>(ph, ah);
    }

    // 3) output projection -> fp32 out
    gemm_mma<<<dim3(DD / 128, BS / 128), 256, gemm_smem>>>(
        ah, w2, b_out, out, nullptr, BS, DD, DD);
}